// round 1
// baseline (speedup 1.0000x reference)
#include <cuda_runtime.h>
#include <cuda_bf16.h>
#include <stdint.h>

#define K_TOTAL 4096
#define N_TOTAL 11008
#define M_TOTAL 512
#define RNK 16

#define M_TILE 128
#define N_TILE 128
#define KC 16
#define NCHUNK (K_TOTAL / KC)   /* 256 */
#define PITCH 12                /* 4-byte words per smem row (24 bf16), conflict-free for frag loads */

__device__ float g_xa[M_TOTAL * RNK];

__constant__ float c_nf4[16] = {
    -1.0f, -0.6961928009986877f, -0.5250730514526367f, -0.39491748809814453f,
    -0.28444138169288635f, -0.18477343022823334f, -0.09105003625154495f, 0.0f,
    0.07958029955625534f, 0.16093020141124725f, 0.24611230194568634f,
    0.33791524171829224f, 0.44070982933044434f, 0.5626170039176941f,
    0.7229568362236023f, 1.0f };

// ---------------------------------------------------------------------------
// Kernel 1: xA = x @ lora_A   -> g_xa [512][16]
// ---------------------------------------------------------------------------
__global__ void xa_kernel(const float* __restrict__ x, const float* __restrict__ A)
{
    int m   = blockIdx.x;        // 0..511
    int tid = threadIdx.x;       // 128 threads
    float acc[RNK];
#pragma unroll
    for (int r = 0; r < RNK; r++) acc[r] = 0.f;

    const float* xr = x + (size_t)m * K_TOTAL;
    for (int k = tid; k < K_TOTAL; k += 128) {
        float xv = xr[k];
        const float* Ar = A + (size_t)k * RNK;
#pragma unroll
        for (int r = 0; r < RNK; r++) acc[r] += xv * Ar[r];
    }
#pragma unroll
    for (int r = 0; r < RNK; r++) {
#pragma unroll
        for (int o = 16; o > 0; o >>= 1)
            acc[r] += __shfl_xor_sync(0xffffffffu, acc[r], o);
    }
    __shared__ float wred[4][RNK];
    int wid = tid >> 5, lane = tid & 31;
    if (lane == 0) {
#pragma unroll
        for (int r = 0; r < RNK; r++) wred[wid][r] = acc[r];
    }
    __syncthreads();
    if (tid < RNK) {
        g_xa[m * RNK + tid] = wred[0][tid] + wred[1][tid] + wred[2][tid] + wred[3][tid];
    }
}

// ---------------------------------------------------------------------------
// Kernel 2: fused NF4 dequant + GEMM (bf16 mma.sync) + bias + LoRA epilogue
// ---------------------------------------------------------------------------
#define MMA_BF16(d0,d1,d2,d3,a0,a1,a2,a3,b0,b1)                               \
    asm volatile("mma.sync.aligned.m16n8k16.row.col.f32.bf16.bf16.f32 "       \
        "{%0,%1,%2,%3}, {%4,%5,%6,%7}, {%8,%9}, {%0,%1,%2,%3};\n"             \
        : "+f"(d0), "+f"(d1), "+f"(d2), "+f"(d3)                              \
        : "r"(a0), "r"(a1), "r"(a2), "r"(a3), "r"(b0), "r"(b1))

__device__ __forceinline__ uint32_t pack_bf16(float a, float b) {
    __nv_bfloat162 p = __floats2bfloat162_rn(a, b);
    return *reinterpret_cast<uint32_t*>(&p);
}

__global__ __launch_bounds__(256, 2)
void qlora_kernel(const float* __restrict__ x,     // [512,4096]
                  const int*   __restrict__ widx,  // [11008,4096]
                  const float* __restrict__ wsc,   // [704512]
                  const float* __restrict__ lB,    // [16,11008]
                  const float* __restrict__ bias,  // [11008]
                  float*       __restrict__ out)   // [512,11008]
{
    __shared__ __align__(16) unsigned char sm_union[16384];
    __shared__ float lut[16];
    __shared__ float bias_s[N_TILE];

    uint32_t* xs32 = reinterpret_cast<uint32_t*>(sm_union);          // bf16 [128][24]
    uint32_t* ws32 = reinterpret_cast<uint32_t*>(sm_union + 6144);   // bf16 [128][24]

    const int tid = threadIdx.x;
    const int m0  = blockIdx.x * M_TILE;   // 4 m tiles (fastest -> co-resident share idx via L2)
    const int n0  = blockIdx.y * N_TILE;   // 86 n tiles

    if (tid < 16)     lut[tid]    = c_nf4[tid];
    if (tid < N_TILE) bias_s[tid] = bias[n0 + tid];

    const int warp = tid >> 5;
    const int lane = tid & 31;
    const int wm   = warp & 3;        // warp m index (0..3) -> rows wm*32
    const int wn   = warp >> 2;       // warp n index (0..1) -> cols wn*64
    const int g    = lane >> 2;       // 0..7
    const int tig  = lane & 3;        // 0..3

    // staging mapping: 64 rows x 4 int4/float4 per pass, two passes (rows +64)
    const int ldr = tid >> 2;         // 0..63
    const int ldc = (tid & 3) << 2;   // 0,4,8,12

    float acc[2][8][4];
#pragma unroll
    for (int a = 0; a < 2; a++)
#pragma unroll
        for (int b = 0; b < 8; b++)
#pragma unroll
            for (int c = 0; c < 4; c++) acc[a][b][c] = 0.f;

    const float* xg = x    + (size_t)(m0 + ldr) * K_TOTAL + ldc;
    const int*   wg = widx + (size_t)(n0 + ldr) * K_TOTAL + ldc;
    const float* sg = wsc  + (size_t)(n0 + ldr) * 64;

    float4 xr[2]; int4 ir[2]; float sr[2];
    // prefetch chunk 0
    xr[0] = *(const float4*)(xg);
    xr[1] = *(const float4*)(xg + (size_t)64 * K_TOTAL);
    ir[0] = *(const int4*)(wg);
    ir[1] = *(const int4*)(wg + (size_t)64 * K_TOTAL);
    sr[0] = sg[0];
    sr[1] = sg[64 * 64];

    for (int ic = 0; ic < NCHUNK; ic++) {
        __syncthreads();
        // convert staged regs -> smem (x: f32->bf16, w: NF4 LUT * scale -> bf16)
#pragma unroll
        for (int h = 0; h < 2; h++) {
            int row  = ldr + h * 64;
            int base = row * PITCH + (ldc >> 1);
            xs32[base]     = pack_bf16(xr[h].x, xr[h].y);
            xs32[base + 1] = pack_bf16(xr[h].z, xr[h].w);
            float s = sr[h];
            ws32[base]     = pack_bf16(lut[ir[h].x & 15] * s, lut[ir[h].y & 15] * s);
            ws32[base + 1] = pack_bf16(lut[ir[h].z & 15] * s, lut[ir[h].w & 15] * s);
        }
        __syncthreads();

        // prefetch chunk ic+1 into registers (overlaps with MMA below)
        if (ic + 1 < NCHUNK) {
            const float* xp = xg + (ic + 1) * KC;
            const int*   wp = wg + (ic + 1) * KC;
            xr[0] = *(const float4*)(xp);
            xr[1] = *(const float4*)(xp + (size_t)64 * K_TOTAL);
            ir[0] = *(const int4*)(wp);
            ir[1] = *(const int4*)(wp + (size_t)64 * K_TOTAL);
            int sb = (ic + 1) >> 2;
            sr[0] = sg[sb];
            sr[1] = sg[64 * 64 + sb];
        }

        // MMA over this 16-wide K chunk
        uint32_t a[2][4];
#pragma unroll
        for (int mt = 0; mt < 2; mt++) {
            int mrow = wm * 32 + mt * 16 + g;
            a[mt][0] = xs32[mrow * PITCH + tig];
            a[mt][1] = xs32[(mrow + 8) * PITCH + tig];
            a[mt][2] = xs32[mrow * PITCH + tig + 4];
            a[mt][3] = xs32[(mrow + 8) * PITCH + tig + 4];
        }
#pragma unroll
        for (int nt = 0; nt < 8; nt++) {
            int nrow = wn * 64 + nt * 8 + g;
            uint32_t b0 = ws32[nrow * PITCH + tig];
            uint32_t b1 = ws32[nrow * PITCH + tig + 4];
            MMA_BF16(acc[0][nt][0], acc[0][nt][1], acc[0][nt][2], acc[0][nt][3],
                     a[0][0], a[0][1], a[0][2], a[0][3], b0, b1);
            MMA_BF16(acc[1][nt][0], acc[1][nt][1], acc[1][nt][2], acc[1][nt][3],
                     a[1][0], a[1][1], a[1][2], a[1][3], b0, b1);
        }
    }

    // ---------------- epilogue: bias + fp32 LoRA rank-16 update ----------------
    __syncthreads();
    float* xa_s = reinterpret_cast<float*>(sm_union);          // [128][16]
    float* bs_s = reinterpret_cast<float*>(sm_union + 8192);   // [16][128]
    for (int j = tid; j < M_TILE * RNK; j += 256) xa_s[j] = g_xa[m0 * RNK + j];
    for (int j = tid; j < RNK * N_TILE; j += 256) {
        int r = j >> 7, n = j & 127;
        bs_s[j] = lB[(size_t)r * N_TOTAL + n0 + n];
    }
    __syncthreads();

#pragma unroll
    for (int mt = 0; mt < 2; mt++) {
        int mlo = wm * 32 + mt * 16 + g;
        int mhi = mlo + 8;
        float xal[16], xah[16];
#pragma unroll
        for (int q = 0; q < 4; q++) {
            float4 v = *(const float4*)&xa_s[mlo * 16 + q * 4];
            xal[q*4+0] = v.x; xal[q*4+1] = v.y; xal[q*4+2] = v.z; xal[q*4+3] = v.w;
            float4 w = *(const float4*)&xa_s[mhi * 16 + q * 4];
            xah[q*4+0] = w.x; xah[q*4+1] = w.y; xah[q*4+2] = w.z; xah[q*4+3] = w.w;
        }
#pragma unroll
        for (int nt = 0; nt < 8; nt++) {
            int nc = wn * 64 + nt * 8 + tig * 2;
            float l00 = 0.f, l01 = 0.f, l10 = 0.f, l11 = 0.f;
#pragma unroll
            for (int r = 0; r < 16; r++) {
                float b0 = bs_s[r * 128 + nc];
                float b1 = bs_s[r * 128 + nc + 1];
                l00 += xal[r] * b0;  l01 += xal[r] * b1;
                l10 += xah[r] * b0;  l11 += xah[r] * b1;
            }
            float bv0 = bias_s[nc], bv1 = bias_s[nc + 1];
            size_t o0 = (size_t)(m0 + mlo) * N_TOTAL + n0 + nc;
            size_t o1 = (size_t)(m0 + mhi) * N_TOTAL + n0 + nc;
            float2 r0, r1;
            r0.x = acc[mt][nt][0] + bv0 + 2.0f * l00;
            r0.y = acc[mt][nt][1] + bv1 + 2.0f * l01;
            r1.x = acc[mt][nt][2] + bv0 + 2.0f * l10;
            r1.y = acc[mt][nt][3] + bv1 + 2.0f * l11;
            *(float2*)&out[o0] = r0;
            *(float2*)&out[o1] = r1;
        }
    }
}

// ---------------------------------------------------------------------------
extern "C" void kernel_launch(void* const* d_in, const int* in_sizes, int n_in,
                              void* d_out, int out_size)
{
    (void)in_sizes; (void)n_in; (void)out_size;
    const float* x    = (const float*)d_in[0];
    const int*   widx = (const int*)  d_in[1];
    const float* wsc  = (const float*)d_in[2];
    const float* lA   = (const float*)d_in[3];
    const float* lB   = (const float*)d_in[4];
    const float* bias = (const float*)d_in[5];
    float* out = (float*)d_out;

    xa_kernel<<<M_TOTAL, 128>>>(x, lA);
    qlora_kernel<<<dim3(M_TOTAL / M_TILE, N_TOTAL / N_TILE), 256>>>(
        x, widx, wsc, lB, bias, out);
}

// round 4
// speedup vs baseline: 1.7981x; 1.7981x over previous
#include <cuda_runtime.h>
#include <cuda_bf16.h>
#include <stdint.h>

#define K_TOTAL 4096
#define N_TOTAL 11008
#define M_TOTAL 512
#define RNK 16

// ---- GEMM tiling ----
#define GM 128
#define GN 128
#define KC 64
#define NCH (K_TOTAL / KC)          /* 64 */
#define STAGES 3
#define A_BYTES (GM * KC * 2)       /* 16384 */
#define B_BYTES (GN * KC * 2)       /* 16384 */
#define STAGE_BYTES (A_BYTES + B_BYTES)          /* 32768 */
#define SMEM_TOTAL (STAGES * STAGE_BYTES)        /* 98304 */

// ---- scratch (device globals: sanctioned scratch, no runtime allocs) ----
__device__ __align__(256) __nv_bfloat16 g_w[(size_t)N_TOTAL * K_TOTAL];  // 90MB dequant W
__device__ __align__(256) __nv_bfloat16 g_xb[(size_t)M_TOTAL * K_TOTAL]; // 4MB x bf16
__device__ __align__(256) float g_xa[M_TOTAL * RNK];

__constant__ float c_nf4[16] = {
    -1.0f, -0.6961928009986877f, -0.5250730514526367f, -0.39491748809814453f,
    -0.28444138169288635f, -0.18477343022823334f, -0.09105003625154495f, 0.0f,
    0.07958029955625534f, 0.16093020141124725f, 0.24611230194568634f,
    0.33791524171829224f, 0.44070982933044434f, 0.5626170039176941f,
    0.7229568362236023f, 1.0f };

__device__ __forceinline__ uint32_t pack2(float a, float b) {
    __nv_bfloat162 p = __floats2bfloat162_rn(a, b);
    return *reinterpret_cast<uint32_t*>(&p);
}

// ---------------------------------------------------------------------------
// xa = x @ lora_A  -> g_xa [512][16]
// ---------------------------------------------------------------------------
__global__ void xa_kernel(const float* __restrict__ x, const float* __restrict__ A)
{
    int m = blockIdx.x, tid = threadIdx.x;
    float acc[RNK];
#pragma unroll
    for (int r = 0; r < RNK; r++) acc[r] = 0.f;
    const float* xr = x + (size_t)m * K_TOTAL;
    for (int k = tid; k < K_TOTAL; k += 128) {
        float xv = xr[k];
        const float* Ar = A + (size_t)k * RNK;
#pragma unroll
        for (int r = 0; r < RNK; r++) acc[r] += xv * Ar[r];
    }
#pragma unroll
    for (int r = 0; r < RNK; r++)
#pragma unroll
        for (int o = 16; o > 0; o >>= 1)
            acc[r] += __shfl_xor_sync(0xffffffffu, acc[r], o);
    __shared__ float wred[4][RNK];
    int wid = tid >> 5, lane = tid & 31;
    if (lane == 0)
#pragma unroll
        for (int r = 0; r < RNK; r++) wred[wid][r] = acc[r];
    __syncthreads();
    if (tid < RNK)
        g_xa[m * RNK + tid] = wred[0][tid] + wred[1][tid] + wred[2][tid] + wred[3][tid];
}

// ---------------------------------------------------------------------------
// x (fp32) -> g_xb (bf16)
// ---------------------------------------------------------------------------
__global__ void xb_kernel(const float* __restrict__ x)
{
    size_t base = ((size_t)blockIdx.x * 256 + threadIdx.x) * 8;
    float4 v0 = *(const float4*)(x + base);
    float4 v1 = *(const float4*)(x + base + 4);
    uint4 o;
    o.x = pack2(v0.x, v0.y); o.y = pack2(v0.z, v0.w);
    o.z = pack2(v1.x, v1.y); o.w = pack2(v1.z, v1.w);
    *reinterpret_cast<uint4*>(g_xb + base) = o;
}

// ---------------------------------------------------------------------------
// Dequant NF4 -> g_w bf16 (shfl LUT, scale folded). 16 elems/thread.
// ---------------------------------------------------------------------------
__global__ void dequant_kernel(const int* __restrict__ widx, const float* __restrict__ wsc)
{
    size_t base = ((size_t)blockIdx.x * 256 + threadIdx.x) * 16;
    int lane = threadIdx.x & 31;
    float lv = c_nf4[lane & 15];
    float s = wsc[base >> 6];
    const int4* ip = reinterpret_cast<const int4*>(widx + base);
    uint32_t o[8];
#pragma unroll
    for (int j = 0; j < 4; j++) {
        int4 v = ip[j];
        float f0 = __shfl_sync(0xffffffffu, lv, v.x) * s;
        float f1 = __shfl_sync(0xffffffffu, lv, v.y) * s;
        float f2 = __shfl_sync(0xffffffffu, lv, v.z) * s;
        float f3 = __shfl_sync(0xffffffffu, lv, v.w) * s;
        o[j * 2]     = pack2(f0, f1);
        o[j * 2 + 1] = pack2(f2, f3);
    }
    uint4* op = reinterpret_cast<uint4*>(g_w + base);
    op[0] = make_uint4(o[0], o[1], o[2], o[3]);
    op[1] = make_uint4(o[4], o[5], o[6], o[7]);
}

// ---------------------------------------------------------------------------
// Legacy-tensor GEMM: out = xb @ g_w^T + bias + 2*(xa @ lB)
// ---------------------------------------------------------------------------
#define MMA_BF16(d,a,b0,b1)                                                   \
    asm volatile("mma.sync.aligned.m16n8k16.row.col.f32.bf16.bf16.f32 "       \
        "{%0,%1,%2,%3}, {%4,%5,%6,%7}, {%8,%9}, {%0,%1,%2,%3};\n"             \
        : "+f"(d[0]), "+f"(d[1]), "+f"(d[2]), "+f"(d[3])                      \
        : "r"(a[0]), "r"(a[1]), "r"(a[2]), "r"(a[3]), "r"(b0), "r"(b1))

static __device__ __forceinline__ void ldsm_x4(uint32_t (&d)[4], uint32_t addr) {
    asm volatile("ldmatrix.sync.aligned.m8n8.x4.shared.b16 {%0,%1,%2,%3}, [%4];"
                 : "=r"(d[0]), "=r"(d[1]), "=r"(d[2]), "=r"(d[3]) : "r"(addr));
}
static __device__ __forceinline__ void cpa16(uint32_t saddr, const void* g) {
    asm volatile("cp.async.cg.shared.global [%0], [%1], 16;" :: "r"(saddr), "l"(g) : "memory");
}

__global__ __launch_bounds__(256, 2)
void gemm_kernel(const float* __restrict__ lB, const float* __restrict__ bias,
                 float* __restrict__ out)
{
    extern __shared__ __align__(128) unsigned char smem[];
    uint32_t sbase;
    asm("{ .reg .u64 t; cvta.to.shared.u64 t, %1; cvt.u32.u64 %0, t; }"
        : "=r"(sbase) : "l"(smem));

    const int tid  = threadIdx.x;
    const int wid  = tid >> 5;
    const int lane = tid & 31;
    const int m0   = blockIdx.x * GM;   // fastest dim: 4 m-tiles share B via L2
    const int n0   = blockIdx.y * GN;

    const int wm = wid >> 2;            // 0..1 -> rows wm*64
    const int wn = wid & 3;             // 0..3 -> cols wn*32
    const int s  = lane & 7;            // swizzle xor key (== row&7 for our rows)
    const int g  = lane >> 3;           // ldmatrix address group 0..3

    // cp.async mapping: q -> row q/8, 16B-chunk q%8
    const int ldr = tid >> 3;
    const int ldc = tid & 7;

    // per-thread ldmatrix row byte-offsets
    int aRow[4], bRow[2];
#pragma unroll
    for (int i = 0; i < 4; i++)
        aRow[i] = (wm * 64 + i * 16 + (g & 1) * 8 + (lane & 7)) * 128;
    const int agk = g >> 1;
#pragma unroll
    for (int p = 0; p < 2; p++)
        bRow[p] = (wn * 32 + p * 16 + (g >> 1) * 8 + (lane & 7)) * 128;
    const int bgk = g & 1;

    float acc[4][4][4];
#pragma unroll
    for (int i = 0; i < 4; i++)
#pragma unroll
        for (int j = 0; j < 4; j++)
#pragma unroll
            for (int e = 0; e < 4; e++) acc[i][j][e] = 0.f;

    // ---- prologue: fill stages 0,1 ----
#pragma unroll
    for (int st = 0; st < STAGES - 1; st++) {
        uint32_t sA = sbase + st * STAGE_BYTES, sB = sA + A_BYTES;
        int k0 = st * KC;
#pragma unroll
        for (int i = 0; i < 4; i++) {
            int r = ldr + i * 32;
            uint32_t dst = r * 128 + ((ldc ^ (r & 7)) << 4);
            cpa16(sA + dst, g_xb + (size_t)(m0 + r) * K_TOTAL + k0 + ldc * 8);
            cpa16(sB + dst, g_w  + (size_t)(n0 + r) * K_TOTAL + k0 + ldc * 8);
        }
        asm volatile("cp.async.commit_group;" ::: "memory");
    }

    for (int ic = 0; ic < NCH; ic++) {
        asm volatile("cp.async.wait_group 1;" ::: "memory");
        __syncthreads();

        // prefetch stage ic+2
        if (ic + 2 < NCH) {
            int st = (ic + 2) % STAGES;
            uint32_t sA = sbase + st * STAGE_BYTES, sB = sA + A_BYTES;
            int k0 = (ic + 2) * KC;
#pragma unroll
            for (int i = 0; i < 4; i++) {
                int r = ldr + i * 32;
                uint32_t dst = r * 128 + ((ldc ^ (r & 7)) << 4);
                cpa16(sA + dst, g_xb + (size_t)(m0 + r) * K_TOTAL + k0 + ldc * 8);
                cpa16(sB + dst, g_w  + (size_t)(n0 + r) * K_TOTAL + k0 + ldc * 8);
            }
        }
        asm volatile("cp.async.commit_group;" ::: "memory");

        // compute stage ic
        uint32_t sA = sbase + (ic % STAGES) * STAGE_BYTES, sB = sA + A_BYTES;
#pragma unroll
        for (int ks = 0; ks < 4; ks++) {
            uint32_t a[4][4], b[2][4];
#pragma unroll
            for (int i = 0; i < 4; i++)
                ldsm_x4(a[i], sA + aRow[i] + (((ks * 2 + agk) ^ s) << 4));
#pragma unroll
            for (int p = 0; p < 2; p++)
                ldsm_x4(b[p], sB + bRow[p] + (((ks * 2 + bgk) ^ s) << 4));
#pragma unroll
            for (int i = 0; i < 4; i++) {
                MMA_BF16(acc[i][0], a[i], b[0][0], b[0][1]);
                MMA_BF16(acc[i][1], a[i], b[0][2], b[0][3]);
                MMA_BF16(acc[i][2], a[i], b[1][0], b[1][1]);
                MMA_BF16(acc[i][3], a[i], b[1][2], b[1][3]);
            }
        }
    }

    // ---------------- epilogue ----------------
    __syncthreads();
    float* lBs    = reinterpret_cast<float*>(smem);                 // [16][128]
    float* xa_s   = lBs + RNK * GN;                                 // [128][16]
    float* bias_s = xa_s + GM * RNK;                                // [128]
    for (int j = tid; j < RNK * GN; j += 256) {
        int r = j >> 7, c = j & 127;
        lBs[j] = lB[(size_t)r * N_TOTAL + n0 + c];
    }
    for (int j = tid; j < GM * RNK; j += 256) xa_s[j] = g_xa[m0 * RNK + j];
    if (tid < GN) bias_s[tid] = bias[n0 + tid];
    __syncthreads();

    const int qr = lane >> 2;        // 0..7
    const int qc = (lane & 3) * 2;   // 0,2,4,6
#pragma unroll
    for (int i = 0; i < 4; i++) {
        int rlo = wm * 64 + i * 16 + qr;
        int rhi = rlo + 8;
        float xal[RNK], xah[RNK];
#pragma unroll
        for (int r = 0; r < RNK; r++) { xal[r] = xa_s[rlo * RNK + r]; xah[r] = xa_s[rhi * RNK + r]; }
#pragma unroll
        for (int j = 0; j < 4; j++) {
            int nc = wn * 32 + j * 8 + qc;
            float l00 = 0.f, l01 = 0.f, l10 = 0.f, l11 = 0.f;
#pragma unroll
            for (int r = 0; r < RNK; r++) {
                float b0 = lBs[r * GN + nc], b1 = lBs[r * GN + nc + 1];
                l00 += xal[r] * b0; l01 += xal[r] * b1;
                l10 += xah[r] * b0; l11 += xah[r] * b1;
            }
            float bv0 = bias_s[nc], bv1 = bias_s[nc + 1];
            float2 r0, r1;
            r0.x = acc[i][j][0] + bv0 + 2.0f * l00;
            r0.y = acc[i][j][1] + bv1 + 2.0f * l01;
            r1.x = acc[i][j][2] + bv0 + 2.0f * l10;
            r1.y = acc[i][j][3] + bv1 + 2.0f * l11;
            *(float2*)&out[(size_t)(m0 + rlo) * N_TOTAL + n0 + nc] = r0;
            *(float2*)&out[(size_t)(m0 + rhi) * N_TOTAL + n0 + nc] = r1;
        }
    }
}

// ---------------------------------------------------------------------------
extern "C" void kernel_launch(void* const* d_in, const int* in_sizes, int n_in,
                              void* d_out, int out_size)
{
    (void)in_sizes; (void)n_in; (void)out_size;
    const float* x    = (const float*)d_in[0];
    const int*   widx = (const int*)  d_in[1];
    const float* wsc  = (const float*)d_in[2];
    const float* lA   = (const float*)d_in[3];
    const float* lB   = (const float*)d_in[4];
    const float* bias = (const float*)d_in[5];
    float* out = (float*)d_out;

    xa_kernel<<<M_TOTAL, 128>>>(x, lA);
    xb_kernel<<<(M_TOTAL * K_TOTAL) / (256 * 8), 256>>>(x);
    dequant_kernel<<<(N_TOTAL * K_TOTAL) / (256 * 16), 256>>>(widx, wsc);

    cudaFuncSetAttribute(gemm_kernel, cudaFuncAttributeMaxDynamicSharedMemorySize, SMEM_TOTAL);
    gemm_kernel<<<dim3(M_TOTAL / GM, N_TOTAL / GN), 256, SMEM_TOTAL>>>(lB, bias, out);
}